// round 11
// baseline (speedup 1.0000x reference)
#include <cuda_runtime.h>
#include <math.h>

#define BB   64
#define TT   512
#define II   64
#define HH   512
#define OO   64
#define TGTN 96

#define NCTA 128
#define NTHR 512

// ---- SMEM layout (floats) ----
#define OFF_ST0   0                   // stage buf 0: 16 batches x 512 = 8192
#define OFF_ST1   8192                // stage buf 1: 8192
#define OFF_GP0   16384               // gate partials K-half 0: 16*65 = 1040
#define OFF_GP1   (OFF_GP0 + 1040)
#define OFF_B0    (OFF_GP1 + 1040)
#define OFF_B1    (OFF_B0 + 16)
#define OFF_C0    (OFF_B1 + 16)       // 256
#define OFF_C1    (OFF_C0 + 256)      // 256
#define OFF_FC    (OFF_C1 + 256)      // 256
#define SMEM_FLOATS (OFF_FC + 256)
#define SMEM_BYTES  (SMEM_FLOATS * 4)

// ---- device globals (no allocation allowed) ----
__device__ float g_hs0[(size_t)TT * BB * HH];  // layer-0 output history
__device__ float g_h1buf[2 * BB * HH];
__device__ float g_h0buf[2 * BB * HH];
__device__ float g_y[BB * OO];
__device__ unsigned g_bar_count;
__device__ unsigned g_bar_gen;

// ---- grid barrier (128 co-resident CTAs) ----
__device__ __forceinline__ void grid_barrier() {
    __syncthreads();
    if (threadIdx.x == 0) {
        __threadfence();
        volatile unsigned* vgen = &g_bar_gen;
        unsigned old = *vgen;
        unsigned arr = atomicAdd(&g_bar_count, 1u);
        if (arr == NCTA - 1) {
            g_bar_count = 0;
            __threadfence();
            atomicExch(&g_bar_gen, old + 1u);
        } else {
            while (*vgen == old) { }
        }
        __threadfence();
    }
    __syncthreads();
}

// ---- packed fp32x2 FMA ----
__device__ __forceinline__ void fma2(unsigned long long& d, unsigned long long a,
                                     unsigned long long b) {
    asm("fma.rn.f32x2 %0, %1, %2, %0;" : "+l"(d) : "l"(a), "l"(b));
}
__device__ __forceinline__ float acc_sum(unsigned long long a) {
    float lo = __uint_as_float((unsigned)(a & 0xffffffffull));
    float hi = __uint_as_float((unsigned)(a >> 32));
    return lo + hi;
}

// ---- cp.async helpers ----
__device__ __forceinline__ void cp16(float* sdst, const float* gsrc) {
    unsigned s = (unsigned)__cvta_generic_to_shared(sdst);
    asm volatile("cp.async.cg.shared.global [%0], [%1], 16;" :: "r"(s), "l"(gsrc));
}
__device__ __forceinline__ void cp_commit() {
    asm volatile("cp.async.commit_group;" ::: "memory");
}
__device__ __forceinline__ void cp_wait0() {
    asm volatile("cp.async.wait_group 0;" ::: "memory");
}

// ---- 16-value butterfly reduce over 16-lane halves + cross-half add.
//      Value index i ends up on lanes (i) and (i+16). ----
__device__ __forceinline__ float reduce16x(float v[16], int lane) {
    const int ks = lane & 15;
#pragma unroll
    for (int o = 8; o >= 1; o >>= 1) {
#pragma unroll
        for (int i = 0; i < o; i++) {
            float a = v[i], b = v[i + o];
            float send = (ks & o) ? a : b;
            float recv = __shfl_xor_sync(0xffffffffu, send, o);
            v[i] = ((ks & o) ? b : a) + recv;
        }
    }
    float r = v[0];
    r += __shfl_xor_sync(0xffffffffu, r, 16);   // combine the two K sub-halves
    return r;
}

// ---- register-resident weight slice: 2 cols x 8 K-floats = 8 u64 ----
// lane K indices within the khp*256 half: {lane*4..+4} and {128+lane*4..+4}
// (16B lane stride -> conflict-free LDS.128 on matching h reads)
struct WReg { unsigned long long w[8]; };

__device__ __forceinline__ void load_wreg(WReg& W, const float* __restrict__ Wmat,
                                          int cta, int cgp, int khp, int lane) {
#pragma unroll
    for (int c = 0; c < 2; c++) {
        int ng = cgp * 2 + c;
        int n  = (ng >> 2) * HH + cta * 4 + (ng & 3);
        const float* base = Wmat + (size_t)n * HH + khp * 256;
        ulonglong2 a  = *(const ulonglong2*)(base + lane * 4);
        ulonglong2 b2 = *(const ulonglong2*)(base + 128 + lane * 4);
        W.w[c * 4 + 0] = a.x;  W.w[c * 4 + 1] = a.y;
        W.w[c * 4 + 2] = b2.x; W.w[c * 4 + 3] = b2.y;
    }
}

__device__ __forceinline__ void load_wx(float wv[2], const float* __restrict__ Wmat,
                                        int cta, int cgp, int khp, int lane) {
#pragma unroll
    for (int c = 0; c < 2; c++) {
        int ng = cgp * 2 + c;
        int n  = (ng >> 2) * HH + cta * 4 + (ng & 3);
        wv[c] = Wmat[(size_t)n * II + khp * 32 + lane];
    }
}

// ---- K=512 GEMM: gate_pre[16 cols x 64 b] partials into plane khp ----
__device__ __forceinline__ void gemm512(
    const float* __restrict__ src, int rstride,   // src[b][k]
    const WReg& W, float* sm, int add,
    int cgp, int khp, int lane)
{
    float* st0 = sm + OFF_ST0;
    float* st1 = sm + OFF_ST1;
    float* sGp = sm + (khp ? OFF_GP1 : OFF_GP0);
    const int tid = threadIdx.x;

    // prefetch chunk 0 (16 batches x 512 floats = 2048 float4)
#pragma unroll
    for (int i = 0; i < 4; i++) {
        int flat = tid + i * NTHR;
        int b = flat >> 7, seg = flat & 127;
        cp16(st0 + b * 512 + seg * 4, src + (size_t)b * rstride + seg * 4);
    }
    cp_commit();

#pragma unroll 1
    for (int ch = 0; ch < 4; ch++) {
        cp_wait0();
        __syncthreads();
        if (ch < 3) {
            float* nb = ((ch + 1) & 1) ? st1 : st0;
#pragma unroll
            for (int i = 0; i < 4; i++) {
                int flat = tid + i * NTHR;
                int b = flat >> 7, seg = flat & 127;
                cp16(nb + b * 512 + seg * 4,
                     src + (size_t)(16 * (ch + 1) + b) * rstride + seg * 4);
            }
            cp_commit();
        }
        const float* S = (ch & 1) ? st1 : st0;
#pragma unroll
        for (int g = 0; g < 2; g++) {
            unsigned long long acc2[16];
#pragma unroll
            for (int i = 0; i < 16; i++) acc2[i] = 0ull;
#pragma unroll
            for (int bb = 0; bb < 8; bb++) {
                const float* row = S + (g * 8 + bb) * 512 + khp * 256;
                ulonglong2 ha = *(const ulonglong2*)(row + lane * 4);
                ulonglong2 hb = *(const ulonglong2*)(row + 128 + lane * 4);
#pragma unroll
                for (int c = 0; c < 2; c++) {
                    unsigned long long* a = &acc2[c * 8 + bb];
                    fma2(*a, ha.x, W.w[c * 4 + 0]);
                    fma2(*a, ha.y, W.w[c * 4 + 1]);
                    fma2(*a, hb.x, W.w[c * 4 + 2]);
                    fma2(*a, hb.y, W.w[c * 4 + 3]);
                }
            }
            float v[16];
#pragma unroll
            for (int i = 0; i < 16; i++) v[i] = acc_sum(acc2[i]);
            float r = reduce16x(v, lane);
            if (lane < 16) {
                int col = cgp * 2 + (lane >> 3);
                int b   = ch * 16 + g * 8 + (lane & 7);
                float* dst = &sGp[col * 65 + b];
                if (add) *dst += r; else *dst = r;
            }
        }
    }
}

// ---- K=64 GEMM (x / y inputs) ----
__device__ __forceinline__ void gemm64(
    const float* __restrict__ src, int rstride,
    const float wv[2], float* sm, int add,
    int cgp, int khp, int lane)
{
    float* st  = sm + OFF_ST0;
    float* sGp = sm + (khp ? OFF_GP1 : OFF_GP0);
    const int tid = threadIdx.x;
#pragma unroll
    for (int i = 0; i < 2; i++) {
        int flat = tid + i * NTHR;          // 0..1023
        int b = flat >> 4, seg = flat & 15; // 16 x 16B per row
        cp16(st + b * 64 + seg * 4, src + (size_t)b * rstride + seg * 4);
    }
    cp_commit();
    cp_wait0();
    __syncthreads();
#pragma unroll
    for (int g = 0; g < 8; g++) {
        float v[16];
#pragma unroll
        for (int bb = 0; bb < 8; bb++) {
            float h = st[(g * 8 + bb) * 64 + khp * 32 + lane];
#pragma unroll
            for (int c = 0; c < 2; c++) v[c * 8 + bb] = wv[c] * h;
        }
        float r = reduce16x(v, lane);
        if (lane < 16) {
            int col = cgp * 2 + (lane >> 3);
            int b   = g * 8 + (lane & 7);
            float* dst = &sGp[col * 65 + b];
            if (add) *dst += r; else *dst = r;
        }
    }
    __syncthreads();   // stage buffer reused immediately by following gemm512
}

// ---- LSTM elementwise (CTA-local 4 hidden units); tid<256 active ----
__device__ __forceinline__ void lstm_elem2(const float* sm, const float* sB,
                                           float* sC, float* __restrict__ dsth,
                                           int cta) {
    int u = threadIdx.x;
    if (u < 256) {
        const float* g0 = sm + OFF_GP0;
        const float* g1 = sm + OFF_GP1;
        int b = u >> 2, jj = u & 3;
        float gi = g0[(0  + jj) * 65 + b] + g1[(0  + jj) * 65 + b] + sB[0  + jj];
        float gf = g0[(4  + jj) * 65 + b] + g1[(4  + jj) * 65 + b] + sB[4  + jj];
        float gg = g0[(8  + jj) * 65 + b] + g1[(8  + jj) * 65 + b] + sB[8  + jj];
        float go = g0[(12 + jj) * 65 + b] + g1[(12 + jj) * 65 + b] + sB[12 + jj];
        float c  = sC[u];
        float si = 1.f / (1.f + expf(-gi));
        float sf = 1.f / (1.f + expf(-gf));
        float so = 1.f / (1.f + expf(-go));
        float cn = sf * c + si * tanhf(gg);
        float hn = so * tanhf(cn);
        sC[u] = cn;
        dsth[b * HH + cta * 4 + jj] = hn;
    }
}

// ---- persistent kernel ----
extern "C" __global__ void __launch_bounds__(NTHR, 1)
lstm_persistent_kernel(
    const float* __restrict__ x,
    const float* __restrict__ Wih0, const float* __restrict__ Whh0,
    const float* __restrict__ bih0, const float* __restrict__ bhh0,
    const float* __restrict__ Wih1, const float* __restrict__ Whh1,
    const float* __restrict__ bih1, const float* __restrict__ bhh1,
    const float* __restrict__ Wfc,  const float* __restrict__ bfc,
    float* __restrict__ out)
{
    extern __shared__ float sm[];
    const int cta  = blockIdx.x;
    const int tid  = threadIdx.x;
    const int wid  = tid >> 5;      // 0..15
    const int lane = tid & 31;
    const int cgp  = wid >> 1;      // 0..7 : 2 gate cols each
    const int khp  = wid & 1;       // K half

    if (tid < 16) {
        int n = (tid >> 2) * HH + cta * 4 + (tid & 3);
        sm[OFF_B0 + tid] = bih0[n] + bhh0[n];
        sm[OFF_B1 + tid] = bih1[n] + bhh1[n];
    }
    if (tid < 256) {
        sm[OFF_C0 + tid] = 0.f;
        sm[OFF_C1 + tid] = 0.f;
    }
    __syncthreads();

    // ================= encoder layer 0 =================
    {
        WReg WH0;  load_wreg(WH0, Whh0, cta, cgp, khp, lane);
        float wx0[2]; load_wx(wx0, Wih0, cta, cgp, khp, lane);
        for (int t = 0; t < TT; t++) {
            gemm64(x + (size_t)t * II, TT * II, wx0, sm, 0, cgp, khp, lane);
            if (t > 0)
                gemm512(g_hs0 + (size_t)(t - 1) * BB * HH, HH, WH0, sm, 1,
                        cgp, khp, lane);
            __syncthreads();
            lstm_elem2(sm, sm + OFF_B0, sm + OFF_C0,
                       g_hs0 + (size_t)t * BB * HH, cta);
            grid_barrier();
        }
    }

    // ================= encoder layer 1 =================
    {
        WReg Wi1;  load_wreg(Wi1, Wih1, cta, cgp, khp, lane);
        WReg Wh1;  load_wreg(Wh1, Whh1, cta, cgp, khp, lane);
        for (int t = 0; t < TT; t++) {
            gemm512(g_hs0 + (size_t)t * BB * HH, HH, Wi1, sm, 0, cgp, khp, lane);
            if (t > 0)
                gemm512(g_h1buf + (size_t)((t - 1) & 1) * BB * HH, HH, Wh1, sm, 1,
                        cgp, khp, lane);
            __syncthreads();
            lstm_elem2(sm, sm + OFF_B1, sm + OFF_C1,
                       g_h1buf + (size_t)(t & 1) * BB * HH, cta);
            grid_barrier();
        }
    }

    // ================= decoder =================
    for (int s = 0; s < TGTN; s++) {
        // phase A : layer-0 cell
        {
            float wx0[2]; load_wx(wx0, Wih0, cta, cgp, khp, lane);
            WReg Wa; load_wreg(Wa, Whh0, cta, cgp, khp, lane);
            const float* xin = (s == 0) ? (x + (size_t)(TT - 1) * II) : g_y;
            int xs = (s == 0) ? (TT * II) : OO;
            gemm64(xin, xs, wx0, sm, 0, cgp, khp, lane);
            const float* hp = (s == 0) ? (g_hs0 + (size_t)(TT - 1) * BB * HH)
                                       : (g_h0buf + (size_t)((s - 1) & 1) * BB * HH);
            gemm512(hp, HH, Wa, sm, 1, cgp, khp, lane);
            __syncthreads();
            lstm_elem2(sm, sm + OFF_B0, sm + OFF_C0,
                       g_h0buf + (size_t)(s & 1) * BB * HH, cta);
            grid_barrier();
        }
        // phase B : layer-1 cell
        {
            WReg Wb; load_wreg(Wb, Wih1, cta, cgp, khp, lane);
            gemm512(g_h0buf + (size_t)(s & 1) * BB * HH, HH, Wb, sm, 0,
                    cgp, khp, lane);
            load_wreg(Wb, Whh1, cta, cgp, khp, lane);
            const float* hp = (s == 0) ? (g_h1buf + (size_t)BB * HH)
                                       : (g_h1buf + (size_t)((s - 1) & 1) * BB * HH);
            gemm512(hp, HH, Wb, sm, 1, cgp, khp, lane);
            __syncthreads();
            lstm_elem2(sm, sm + OFF_B1, sm + OFF_C1,
                       g_h1buf + (size_t)(s & 1) * BB * HH, cta);
            grid_barrier();
        }
        // phase C : y = h1 @ Wfc^T + bfc
        {
            float* sFc = sm + OFF_FC;
            const float* h1 = g_h1buf + (size_t)(s & 1) * BB * HH;
            if (tid < 256) {
                int p = tid >> 3, q = tid & 7;     // 32 outputs/CTA, 8-way K split
                int flat = cta * 32 + p;           // 4096 = 64 b x 64 o
                int bb = flat >> 6, oo = flat & 63;
                const float4* h4 = (const float4*)(h1 + (size_t)bb * HH + q * 64);
                const float4* w4 = (const float4*)(Wfc + (size_t)oo * HH + q * 64);
                float sum = 0.f;
#pragma unroll
                for (int k = 0; k < 16; k++) {
                    float4 a = h4[k], w = w4[k];
                    sum += a.x * w.x + a.y * w.y + a.z * w.z + a.w * w.w;
                }
                sFc[p * 8 + q] = sum;
            }
            __syncthreads();
            if (tid < 32) {
                int fl = cta * 32 + tid;
                int bb2 = fl >> 6, oo2 = fl & 63;
                float tot = bfc[oo2];
#pragma unroll
                for (int j = 0; j < 8; j++) tot += sFc[tid * 8 + j];
                g_y[bb2 * OO + oo2] = tot;
                out[(size_t)bb2 * TGTN * OO + (size_t)s * OO + oo2] = tot;
            }
            grid_barrier();
        }
    }
}

// ---- host launch ----
extern "C" void kernel_launch(void* const* d_in, const int* in_sizes, int n_in,
                              void* d_out, int out_size) {
    (void)in_sizes; (void)n_in; (void)out_size;
    const float* x    = (const float*)d_in[0];
    const float* Wih0 = (const float*)d_in[1];
    const float* Whh0 = (const float*)d_in[2];
    const float* bih0 = (const float*)d_in[3];
    const float* bhh0 = (const float*)d_in[4];
    const float* Wih1 = (const float*)d_in[5];
    const float* Whh1 = (const float*)d_in[6];
    const float* bih1 = (const float*)d_in[7];
    const float* bhh1 = (const float*)d_in[8];
    const float* Wfc  = (const float*)d_in[9];
    const float* bfc  = (const float*)d_in[10];

    cudaFuncSetAttribute(lstm_persistent_kernel,
                         cudaFuncAttributeMaxDynamicSharedMemorySize, SMEM_BYTES);
    lstm_persistent_kernel<<<NCTA, NTHR, SMEM_BYTES>>>(
        x, Wih0, Whh0, bih0, bhh0, Wih1, Whh1, bih1, bhh1, Wfc, bfc,
        (float*)d_out);
}

// round 13
// speedup vs baseline: 1.5936x; 1.5936x over previous
#include <cuda_runtime.h>
#include <math.h>

#define BB   64
#define TT   512
#define II   64
#define HH   512
#define OO   64
#define TGTN 96

#define NCTA 128
#define NTHR 512

// ---- SMEM layout (floats) ----
#define OFF_ST0   0                   // stage buf 0: 16 batches x 512 = 8192
#define OFF_ST1   8192                // stage buf 1: 8192
#define OFF_GP0   16384               // gate partials K-half 0: 16*65 = 1040
#define OFF_GP1   (OFF_GP0 + 1040)
#define OFF_B0    (OFF_GP1 + 1040)
#define OFF_B1    (OFF_B0 + 16)
#define OFF_C0    (OFF_B1 + 16)       // 256
#define OFF_C1    (OFF_C0 + 256)      // 256
#define OFF_FC    (OFF_C1 + 256)      // 256
#define SMEM_FLOATS (OFF_FC + 256)
#define SMEM_BYTES  (SMEM_FLOATS * 4)

// ---- device globals (no allocation allowed) ----
__device__ float g_hs0[(size_t)TT * BB * HH];  // layer-0 output history
__device__ float g_h1buf[2 * BB * HH];
__device__ float g_h0buf[2 * BB * HH];
__device__ float g_y[BB * OO];
__device__ unsigned g_bar_count;
__device__ unsigned g_bar_gen;

// ---- grid barrier (128 co-resident CTAs) ----
__device__ __forceinline__ void grid_barrier() {
    __syncthreads();
    if (threadIdx.x == 0) {
        __threadfence();
        volatile unsigned* vgen = &g_bar_gen;
        unsigned old = *vgen;
        unsigned arr = atomicAdd(&g_bar_count, 1u);
        if (arr == NCTA - 1) {
            g_bar_count = 0;
            __threadfence();
            atomicExch(&g_bar_gen, old + 1u);
        } else {
            while (*vgen == old) { }
        }
        __threadfence();
    }
    __syncthreads();
}

// ---- packed fp32x2 FMA ----
__device__ __forceinline__ void fma2(unsigned long long& d, unsigned long long a,
                                     unsigned long long b) {
    asm("fma.rn.f32x2 %0, %1, %2, %0;" : "+l"(d) : "l"(a), "l"(b));
}
__device__ __forceinline__ float acc_sum(unsigned long long a) {
    float lo = __uint_as_float((unsigned)(a & 0xffffffffull));
    float hi = __uint_as_float((unsigned)(a >> 32));
    return lo + hi;
}

// ---- cp.async helpers ----
__device__ __forceinline__ void cp16(float* sdst, const float* gsrc) {
    unsigned s = (unsigned)__cvta_generic_to_shared(sdst);
    asm volatile("cp.async.cg.shared.global [%0], [%1], 16;" :: "r"(s), "l"(gsrc));
}
__device__ __forceinline__ void cp_commit() {
    asm volatile("cp.async.commit_group;" ::: "memory");
}
__device__ __forceinline__ void cp_wait0() {
    asm volatile("cp.async.wait_group 0;" ::: "memory");
}

// ---- 16-value butterfly reduce over 16-lane halves + cross-half add.
//      Value index i ends up on lanes (i) and (i+16). ----
__device__ __forceinline__ float reduce16x(float v[16], int lane) {
    const int ks = lane & 15;
#pragma unroll
    for (int o = 8; o >= 1; o >>= 1) {
#pragma unroll
        for (int i = 0; i < o; i++) {
            float a = v[i], b = v[i + o];
            float send = (ks & o) ? a : b;
            float recv = __shfl_xor_sync(0xffffffffu, send, o);
            v[i] = ((ks & o) ? b : a) + recv;
        }
    }
    float r = v[0];
    r += __shfl_xor_sync(0xffffffffu, r, 16);   // combine the two K sub-halves
    return r;
}

// ---- register-resident weight slice: 2 cols x 8 K-floats = 8 u64 ----
// lane K indices within the khp*256 half: {lane*4..+4} and {128+lane*4..+4}
// (16B lane stride -> conflict-free LDS.128 on matching h reads)
struct WReg { unsigned long long w[8]; };

__device__ __forceinline__ void load_wreg(WReg& W, const float* __restrict__ Wmat,
                                          int cta, int cgp, int khp, int lane) {
#pragma unroll
    for (int c = 0; c < 2; c++) {
        int ng = cgp * 2 + c;
        int n  = (ng >> 2) * HH + cta * 4 + (ng & 3);
        const float* base = Wmat + (size_t)n * HH + khp * 256;
        ulonglong2 a  = *(const ulonglong2*)(base + lane * 4);
        ulonglong2 b2 = *(const ulonglong2*)(base + 128 + lane * 4);
        W.w[c * 4 + 0] = a.x;  W.w[c * 4 + 1] = a.y;
        W.w[c * 4 + 2] = b2.x; W.w[c * 4 + 3] = b2.y;
    }
}

__device__ __forceinline__ void load_wx(float wv[2], const float* __restrict__ Wmat,
                                        int cta, int cgp, int khp, int lane) {
#pragma unroll
    for (int c = 0; c < 2; c++) {
        int ng = cgp * 2 + c;
        int n  = (ng >> 2) * HH + cta * 4 + (ng & 3);
        wv[c] = Wmat[(size_t)n * II + khp * 32 + lane];
    }
}

// ---- K=512 GEMM: gate_pre[16 cols x 64 b] partials into plane khp ----
__device__ __forceinline__ void gemm512(
    const float* __restrict__ src, int rstride,   // src[b][k]
    const WReg& W, float* sm, int add,
    int cgp, int khp, int lane)
{
    float* st0 = sm + OFF_ST0;
    float* st1 = sm + OFF_ST1;
    float* sGp = sm + (khp ? OFF_GP1 : OFF_GP0);
    const int tid = threadIdx.x;

    // prefetch chunk 0 (16 batches x 512 floats = 2048 float4)
#pragma unroll
    for (int i = 0; i < 4; i++) {
        int flat = tid + i * NTHR;
        int b = flat >> 7, seg = flat & 127;
        cp16(st0 + b * 512 + seg * 4, src + (size_t)b * rstride + seg * 4);
    }
    cp_commit();

#pragma unroll 1
    for (int ch = 0; ch < 4; ch++) {
        cp_wait0();
        __syncthreads();
        if (ch < 3) {
            float* nb = ((ch + 1) & 1) ? st1 : st0;
#pragma unroll
            for (int i = 0; i < 4; i++) {
                int flat = tid + i * NTHR;
                int b = flat >> 7, seg = flat & 127;
                cp16(nb + b * 512 + seg * 4,
                     src + (size_t)(16 * (ch + 1) + b) * rstride + seg * 4);
            }
            cp_commit();
        }
        const float* S = (ch & 1) ? st1 : st0;
#pragma unroll
        for (int g = 0; g < 2; g++) {
            unsigned long long acc2[16];
#pragma unroll
            for (int i = 0; i < 16; i++) acc2[i] = 0ull;
#pragma unroll
            for (int bb = 0; bb < 8; bb++) {
                const float* row = S + (g * 8 + bb) * 512 + khp * 256;
                ulonglong2 ha = *(const ulonglong2*)(row + lane * 4);
                ulonglong2 hb = *(const ulonglong2*)(row + 128 + lane * 4);
#pragma unroll
                for (int c = 0; c < 2; c++) {
                    unsigned long long* a = &acc2[c * 8 + bb];
                    fma2(*a, ha.x, W.w[c * 4 + 0]);
                    fma2(*a, ha.y, W.w[c * 4 + 1]);
                    fma2(*a, hb.x, W.w[c * 4 + 2]);
                    fma2(*a, hb.y, W.w[c * 4 + 3]);
                }
            }
            float v[16];
#pragma unroll
            for (int i = 0; i < 16; i++) v[i] = acc_sum(acc2[i]);
            float r = reduce16x(v, lane);
            if (lane < 16) {
                int col = cgp * 2 + (lane >> 3);
                int b   = ch * 16 + g * 8 + (lane & 7);
                float* dst = &sGp[col * 65 + b];
                if (add) *dst += r; else *dst = r;
            }
        }
    }
}

// ---- K=64 GEMM (x / y inputs) ----
__device__ __forceinline__ void gemm64(
    const float* __restrict__ src, int rstride,
    const float wv[2], float* sm, int add,
    int cgp, int khp, int lane)
{
    float* st  = sm + OFF_ST0;
    float* sGp = sm + (khp ? OFF_GP1 : OFF_GP0);
    const int tid = threadIdx.x;
#pragma unroll
    for (int i = 0; i < 2; i++) {
        int flat = tid + i * NTHR;          // 0..1023
        int b = flat >> 4, seg = flat & 15; // 16 x 16B per row
        cp16(st + b * 64 + seg * 4, src + (size_t)b * rstride + seg * 4);
    }
    cp_commit();
    cp_wait0();
    __syncthreads();
#pragma unroll
    for (int g = 0; g < 8; g++) {
        float v[16];
#pragma unroll
        for (int bb = 0; bb < 8; bb++) {
            float h = st[(g * 8 + bb) * 64 + khp * 32 + lane];
#pragma unroll
            for (int c = 0; c < 2; c++) v[c * 8 + bb] = wv[c] * h;
        }
        float r = reduce16x(v, lane);
        if (lane < 16) {
            int col = cgp * 2 + (lane >> 3);
            int b   = g * 8 + (lane & 7);
            float* dst = &sGp[col * 65 + b];
            if (add) *dst += r; else *dst = r;
        }
    }
    __syncthreads();   // stage buffer reused immediately by following gemm512
}

// ---- LSTM elementwise (CTA-local 4 hidden units); tid<256 active ----
__device__ __forceinline__ void lstm_elem2(const float* sm, const float* sB,
                                           float* sC, float* __restrict__ dsth,
                                           int cta) {
    int u = threadIdx.x;
    if (u < 256) {
        const float* g0 = sm + OFF_GP0;
        const float* g1 = sm + OFF_GP1;
        int b = u >> 2, jj = u & 3;
        float gi = g0[(0  + jj) * 65 + b] + g1[(0  + jj) * 65 + b] + sB[0  + jj];
        float gf = g0[(4  + jj) * 65 + b] + g1[(4  + jj) * 65 + b] + sB[4  + jj];
        float gg = g0[(8  + jj) * 65 + b] + g1[(8  + jj) * 65 + b] + sB[8  + jj];
        float go = g0[(12 + jj) * 65 + b] + g1[(12 + jj) * 65 + b] + sB[12 + jj];
        float c  = sC[u];
        float si = 1.f / (1.f + expf(-gi));
        float sf = 1.f / (1.f + expf(-gf));
        float so = 1.f / (1.f + expf(-go));
        float cn = sf * c + si * tanhf(gg);
        float hn = so * tanhf(cn);
        sC[u] = cn;
        dsth[b * HH + cta * 4 + jj] = hn;
    }
}

// ---- persistent kernel ----
extern "C" __global__ void __launch_bounds__(NTHR, 1)
lstm_persistent_kernel(
    const float* __restrict__ x,
    const float* __restrict__ Wih0, const float* __restrict__ Whh0,
    const float* __restrict__ bih0, const float* __restrict__ bhh0,
    const float* __restrict__ Wih1, const float* __restrict__ Whh1,
    const float* __restrict__ bih1, const float* __restrict__ bhh1,
    const float* __restrict__ Wfc,  const float* __restrict__ bfc,
    float* __restrict__ out)
{
    extern __shared__ float sm[];
    const int cta  = blockIdx.x;
    const int tid  = threadIdx.x;
    const int wid  = tid >> 5;      // 0..15
    const int lane = tid & 31;
    const int cgp  = wid >> 1;      // 0..7 : 2 gate cols each
    const int khp  = wid & 1;       // K half

    if (tid < 16) {
        int n = (tid >> 2) * HH + cta * 4 + (tid & 3);
        sm[OFF_B0 + tid] = bih0[n] + bhh0[n];
        sm[OFF_B1 + tid] = bih1[n] + bhh1[n];
    }
    if (tid < 256) {
        sm[OFF_C0 + tid] = 0.f;
        sm[OFF_C1 + tid] = 0.f;
    }
    __syncthreads();

    // ================= encoder layer 0 =================
    {
        WReg WH0;  load_wreg(WH0, Whh0, cta, cgp, khp, lane);
        float wx0[2]; load_wx(wx0, Wih0, cta, cgp, khp, lane);
        for (int t = 0; t < TT; t++) {
            gemm64(x + (size_t)t * II, TT * II, wx0, sm, 0, cgp, khp, lane);
            if (t > 0)
                gemm512(g_hs0 + (size_t)(t - 1) * BB * HH, HH, WH0, sm, 1,
                        cgp, khp, lane);
            __syncthreads();
            lstm_elem2(sm, sm + OFF_B0, sm + OFF_C0,
                       g_hs0 + (size_t)t * BB * HH, cta);
            grid_barrier();
        }
    }

    // ================= encoder layer 1 =================
    {
        WReg Wi1;  load_wreg(Wi1, Wih1, cta, cgp, khp, lane);
        WReg Wh1;  load_wreg(Wh1, Whh1, cta, cgp, khp, lane);
        for (int t = 0; t < TT; t++) {
            gemm512(g_hs0 + (size_t)t * BB * HH, HH, Wi1, sm, 0, cgp, khp, lane);
            if (t > 0)
                gemm512(g_h1buf + (size_t)((t - 1) & 1) * BB * HH, HH, Wh1, sm, 1,
                        cgp, khp, lane);
            __syncthreads();
            lstm_elem2(sm, sm + OFF_B1, sm + OFF_C1,
                       g_h1buf + (size_t)(t & 1) * BB * HH, cta);
            grid_barrier();
        }
    }

    // ================= decoder =================
    for (int s = 0; s < TGTN; s++) {
        // phase A : layer-0 cell
        {
            float wx0[2]; load_wx(wx0, Wih0, cta, cgp, khp, lane);
            WReg Wa; load_wreg(Wa, Whh0, cta, cgp, khp, lane);
            const float* xin = (s == 0) ? (x + (size_t)(TT - 1) * II) : g_y;
            int xs = (s == 0) ? (TT * II) : OO;
            gemm64(xin, xs, wx0, sm, 0, cgp, khp, lane);
            const float* hp = (s == 0) ? (g_hs0 + (size_t)(TT - 1) * BB * HH)
                                       : (g_h0buf + (size_t)((s - 1) & 1) * BB * HH);
            gemm512(hp, HH, Wa, sm, 1, cgp, khp, lane);
            __syncthreads();
            lstm_elem2(sm, sm + OFF_B0, sm + OFF_C0,
                       g_h0buf + (size_t)(s & 1) * BB * HH, cta);
            grid_barrier();
        }
        // phase B : layer-1 cell
        {
            WReg Wb; load_wreg(Wb, Wih1, cta, cgp, khp, lane);
            gemm512(g_h0buf + (size_t)(s & 1) * BB * HH, HH, Wb, sm, 0,
                    cgp, khp, lane);
            load_wreg(Wb, Whh1, cta, cgp, khp, lane);
            const float* hp = (s == 0) ? (g_h1buf + (size_t)BB * HH)
                                       : (g_h1buf + (size_t)((s - 1) & 1) * BB * HH);
            gemm512(hp, HH, Wb, sm, 1, cgp, khp, lane);
            __syncthreads();
            lstm_elem2(sm, sm + OFF_B1, sm + OFF_C1,
                       g_h1buf + (size_t)(s & 1) * BB * HH, cta);
            grid_barrier();
        }
        // phase C : y = h1 @ Wfc^T + bfc
        {
            float* sFc = sm + OFF_FC;
            const float* h1 = g_h1buf + (size_t)(s & 1) * BB * HH;
            if (tid < 256) {
                int p = tid >> 3, q = tid & 7;     // 32 outputs/CTA, 8-way K split
                int flat = cta * 32 + p;           // 4096 = 64 b x 64 o
                int bb = flat >> 6, oo = flat & 63;
                const float4* h4 = (const float4*)(h1 + (size_t)bb * HH + q * 64);
                const float4* w4 = (const float4*)(Wfc + (size_t)oo * HH + q * 64);
                float sum = 0.f;
#pragma unroll
                for (int k = 0; k < 16; k++) {
                    float4 a = h4[k], w = w4[k];
                    sum += a.x * w.x + a.y * w.y + a.z * w.z + a.w * w.w;
                }
                sFc[p * 8 + q] = sum;
            }
            __syncthreads();
            if (tid < 32) {
                int fl = cta * 32 + tid;
                int bb2 = fl >> 6, oo2 = fl & 63;
                float tot = bfc[oo2];
#pragma unroll
                for (int j = 0; j < 8; j++) tot += sFc[tid * 8 + j];
                g_y[bb2 * OO + oo2] = tot;
                out[(size_t)bb2 * TGTN * OO + (size_t)s * OO + oo2] = tot;
            }
            grid_barrier();
        }
    }
}

// ---- host launch ----
extern "C" void kernel_launch(void* const* d_in, const int* in_sizes, int n_in,
                              void* d_out, int out_size) {
    (void)in_sizes; (void)n_in; (void)out_size;
    const float* x    = (const float*)d_in[0];
    const float* Wih0 = (const float*)d_in[1];
    const float* Whh0 = (const float*)d_in[2];
    const float* bih0 = (const float*)d_in[3];
    const float* bhh0 = (const float*)d_in[4];
    const float* Wih1 = (const float*)d_in[5];
    const float* Whh1 = (const float*)d_in[6];
    const float* bih1 = (const float*)d_in[7];
    const float* bhh1 = (const float*)d_in[8];
    const float* Wfc  = (const float*)d_in[9];
    const float* bfc  = (const float*)d_in[10];

    cudaFuncSetAttribute(lstm_persistent_kernel,
                         cudaFuncAttributeMaxDynamicSharedMemorySize, SMEM_BYTES);
    lstm_persistent_kernel<<<NCTA, NTHR, SMEM_BYTES>>>(
        x, Wih0, Whh0, bih0, bhh0, Wih1, Whh1, bih1, bhh1, Wfc, bfc,
        (float*)d_out);
}

// round 15
// speedup vs baseline: 2.6615x; 1.6701x over previous
#include <cuda_runtime.h>
#include <math.h>

#define BB 64
#define TT 512
#define II 64
#define HH 512
#define OO 64
#define TGTN 96
#define NCTA 128
#define NTHR 256

typedef unsigned long long ull;

// ---- SMEM layout (floats) ----
#define OFF_WHH0 0            // 512*16 = 8192
#define OFF_WIH1 8192
#define OFF_WHH1 16384
#define OFF_WX   24576        // 64*16 = 1024
#define OFF_ST0  25600        // chunk stage 128k x 64b = 8192
#define OFF_ST1  33792
#define OFF_G    41984        // 512 u64 = 1024 floats
#define OFF_B0   43008
#define OFF_B1   43024
#define OFF_C0   43040        // 256
#define OFF_C1   43296        // 256
#define OFF_FC   43552        // 256
#define SMEM_FLOATS 43808
#define SMEM_BYTES (SMEM_FLOATS * 4)

// ---- device globals ----
__device__ float g_hs0[(size_t)TT * HH * BB];     // [t][j][b] k-major
__device__ float g_h0buf[2 * HH * BB];
__device__ float g_h1buf[2 * HH * BB];
__device__ float g_h1T[BB * HH];                  // [b][j] for fc
__device__ float g_y[OO * BB];                    // [o][b]
__device__ float g_xT[(size_t)TT * II * BB];      // [t][i][b]
__device__ float g_wt_hh0[(size_t)NCTA * HH * 16];
__device__ float g_wt_ih1[(size_t)NCTA * HH * 16];
__device__ float g_wt_hh1[(size_t)NCTA * HH * 16];
__device__ float g_wt_ih0[(size_t)NCTA * II * 16];
__device__ unsigned g_bar_count;
__device__ unsigned g_bar_gen;

__device__ __forceinline__ void grid_barrier() {
    __syncthreads();
    if (threadIdx.x == 0) {
        __threadfence();
        volatile unsigned* vgen = &g_bar_gen;
        unsigned old = *vgen;
        unsigned arr = atomicAdd(&g_bar_count, 1u);
        if (arr == NCTA - 1) {
            g_bar_count = 0;
            __threadfence();
            atomicExch(&g_bar_gen, old + 1u);
        } else {
            while (*vgen == old) { }
        }
        __threadfence();
    }
    __syncthreads();
}

__device__ __forceinline__ void fma2(ull& d, ull a, ull b) {
    asm("fma.rn.f32x2 %0, %1, %2, %0;" : "+l"(d) : "l"(a), "l"(b));
}
__device__ __forceinline__ ull addx2(ull a, ull b) {
    ull r;
    asm("add.rn.f32x2 %0, %1, %2;" : "=l"(r) : "l"(a), "l"(b));
    return r;
}
__device__ __forceinline__ ull dup2(float w) {
    ull r;
    asm("mov.b64 %0, {%1, %1};" : "=l"(r) : "f"(w));
    return r;
}
__device__ __forceinline__ void cp16(float* sdst, const float* gsrc) {
    unsigned s = (unsigned)__cvta_generic_to_shared(sdst);
    asm volatile("cp.async.cg.shared.global [%0], [%1], 16;" :: "r"(s), "l"(gsrc));
}
__device__ __forceinline__ void cp_commit() {
    asm volatile("cp.async.commit_group;" ::: "memory");
}
__device__ __forceinline__ void cp_wait0() {
    asm volatile("cp.async.wait_group 0;" ::: "memory");
}

// ---- one k-row tile: 4 cols x 4 batch-pairs ----
__device__ __forceinline__ void tile_k(const float* hr, const float* wr, ull* acc) {
    ulonglong2 h01 = *(const ulonglong2*)hr;
    ulonglong2 h23 = *(const ulonglong2*)(hr + 4);
    float4 wv = *(const float4*)wr;
    ull w0 = dup2(wv.x), w1 = dup2(wv.y), w2 = dup2(wv.z), w3 = dup2(wv.w);
    fma2(acc[0],  h01.x, w0); fma2(acc[1],  h01.y, w0);
    fma2(acc[2],  h23.x, w0); fma2(acc[3],  h23.y, w0);
    fma2(acc[4],  h01.x, w1); fma2(acc[5],  h01.y, w1);
    fma2(acc[6],  h23.x, w1); fma2(acc[7],  h23.y, w1);
    fma2(acc[8],  h01.x, w2); fma2(acc[9],  h01.y, w2);
    fma2(acc[10], h23.x, w2); fma2(acc[11], h23.y, w2);
    fma2(acc[12], h01.x, w3); fma2(acc[13], h01.y, w3);
    fma2(acc[14], h23.x, w3); fma2(acc[15], h23.y, w3);
}

// ---- K=512 GEMM, accumulate into acc (no reduction here) ----
// hsrc: [512][64] k-major global. sW: [512][16] in SMEM.
__device__ void g512(const float* __restrict__ hsrc, const float* sW, float* sm,
                     ull* acc, int warp, int cq, int bp8) {
    const int tid = threadIdx.x;
    float* st0 = sm + OFF_ST0;
    float* st1 = sm + OFF_ST1;
#pragma unroll
    for (int i = 0; i < 8; i++) {
        int f = tid + i * NTHR;            // 0..2047 float4s
        cp16(st0 + f * 4, hsrc + f * 4);
    }
    cp_commit();
#pragma unroll 1
    for (int ch = 0; ch < 4; ch++) {
        cp_wait0();
        __syncthreads();
        if (ch < 3) {
            float* nb = ((ch + 1) & 1) ? st1 : st0;
            const float* ns = hsrc + (ch + 1) * 8192;
#pragma unroll
            for (int i = 0; i < 8; i++) {
                int f = tid + i * NTHR;
                cp16(nb + f * 4, ns + f * 4);
            }
            cp_commit();
        }
        const float* S  = (ch & 1) ? st1 : st0;
        const float* Wc = sW + ch * 128 * 16;
#pragma unroll
        for (int i = 0; i < 16; i++) {
            int k = warp * 16 + i;
            tile_k(S + k * 64 + bp8 * 8, Wc + k * 16 + cq * 4, acc);
        }
    }
    __syncthreads();   // stage reusable after this
}

// ---- K=64 GEMM (x / y part); src: [64][64] k-major ----
__device__ void g64(const float* __restrict__ src, const float* sWX, float* sm,
                    ull* acc, int warp, int cq, int bp8) {
    const int tid = threadIdx.x;
    float* st = sm + OFF_ST0;
#pragma unroll
    for (int i = 0; i < 4; i++) {
        int f = tid + i * NTHR;            // 0..1023 float4s
        cp16(st + f * 4, src + f * 4);
    }
    cp_commit();
    cp_wait0();
    __syncthreads();
#pragma unroll
    for (int i = 0; i < 8; i++) {
        int k = warp * 8 + i;
        tile_k(st + k * 64 + bp8 * 8, sWX + k * 16 + cq * 4, acc);
    }
    __syncthreads();
}

// ---- step finish: cross-warp reduce + LSTM elementwise + state write ----
__device__ void step_finish(float* sm, ull* acc, int warp, int cq, int bp8,
                            const float* sB, float* sC, int cta,
                            float* __restrict__ dstK,      // [512][64] slice target
                            float* __restrict__ dstT) {    // optional [b][512] copy
    const int tid = threadIdx.x;
    ull* sRed = (ull*)(sm + OFF_ST0);      // 8 x 512 u64 = 32KB (aliases stage)
#pragma unroll
    for (int c = 0; c < 4; c++)
#pragma unroll
        for (int i = 0; i < 4; i++)
            sRed[warp * 512 + (cq * 4 + c) * 32 + bp8 * 4 + i] = acc[c * 4 + i];
    __syncthreads();
    ull* sG = (ull*)(sm + OFF_G);
#pragma unroll
    for (int t2 = 0; t2 < 2; t2++) {
        int u = tid * 2 + t2;
        ull s = sRed[u];
#pragma unroll
        for (int w = 1; w < 8; w++) s = addx2(s, sRed[w * 512 + u]);
        sG[u] = s;
    }
    __syncthreads();
    // elementwise: tid = jj*64 + b
    const float* gf = sm + OFF_G;
    int b = tid & 63, jj = tid >> 6;
    float gi = gf[(0  + jj) * 64 + b] + sB[0  + jj];
    float gfo = gf[(4 + jj) * 64 + b] + sB[4  + jj];
    float gg = gf[(8  + jj) * 64 + b] + sB[8  + jj];
    float go = gf[(12 + jj) * 64 + b] + sB[12 + jj];
    float c  = sC[tid];
    float si = 1.f / (1.f + expf(-gi));
    float sf = 1.f / (1.f + expf(-gfo));
    float so = 1.f / (1.f + expf(-go));
    float cn = sf * c + si * tanhf(gg);
    float hn = so * tanhf(cn);
    sC[tid] = cn;
    int j = cta * 4 + jj;
    dstK[j * 64 + b] = hn;
    if (dstT) dstT[(size_t)b * HH + j] = hn;
    grid_barrier();
}

// ---- prep kernels ----
extern "C" __global__ void prep_w_kernel(
    const float* __restrict__ Wih0, const float* __restrict__ Whh0,
    const float* __restrict__ Wih1, const float* __restrict__ Whh1) {
    int cta = blockIdx.x, tid = threadIdx.x;
    for (int idx = tid; idx < 512 * 16; idx += NTHR) {
        int k = idx >> 4, ng = idx & 15;
        int n = (ng >> 2) * HH + cta * 4 + (ng & 3);
        g_wt_hh0[(size_t)cta * 8192 + idx] = Whh0[(size_t)n * HH + k];
        g_wt_ih1[(size_t)cta * 8192 + idx] = Wih1[(size_t)n * HH + k];
        g_wt_hh1[(size_t)cta * 8192 + idx] = Whh1[(size_t)n * HH + k];
    }
    for (int idx = tid; idx < 64 * 16; idx += NTHR) {
        int k = idx >> 4, ng = idx & 15;
        int n = (ng >> 2) * HH + cta * 4 + (ng & 3);
        g_wt_ih0[(size_t)cta * 1024 + idx] = Wih0[(size_t)n * II + k];
    }
}
extern "C" __global__ void prep_x_kernel(const float* __restrict__ x) {
    int t = blockIdx.x, tid = threadIdx.x;
    for (int idx = tid; idx < 64 * 64; idx += NTHR) {
        int i = idx >> 6, b = idx & 63;
        g_xT[(size_t)t * 4096 + i * 64 + b] = x[(size_t)b * TT * II + t * II + i];
    }
}

// ---- main persistent kernel ----
extern "C" __global__ void __launch_bounds__(NTHR, 1)
lstm_persistent_kernel(
    const float* __restrict__ bih0, const float* __restrict__ bhh0,
    const float* __restrict__ bih1, const float* __restrict__ bhh1,
    const float* __restrict__ Wfc,  const float* __restrict__ bfc,
    float* __restrict__ out)
{
    extern __shared__ float sm[];
    const int cta  = blockIdx.x;
    const int tid  = threadIdx.x;
    const int warp = tid >> 5;
    const int lane = tid & 31;
    const int bp8  = lane >> 2;     // 0..7 : batch octet
    const int cq   = lane & 3;      // 0..3 : col quad

    // load persistent weights to SMEM
    for (int idx = tid; idx < 8192; idx += NTHR) {
        sm[OFF_WHH0 + idx] = g_wt_hh0[(size_t)cta * 8192 + idx];
        sm[OFF_WIH1 + idx] = g_wt_ih1[(size_t)cta * 8192 + idx];
        sm[OFF_WHH1 + idx] = g_wt_hh1[(size_t)cta * 8192 + idx];
    }
    for (int idx = tid; idx < 1024; idx += NTHR)
        sm[OFF_WX + idx] = g_wt_ih0[(size_t)cta * 1024 + idx];
    if (tid < 16) {
        int n = (tid >> 2) * HH + cta * 4 + (tid & 3);
        sm[OFF_B0 + tid] = bih0[n] + bhh0[n];
        sm[OFF_B1 + tid] = bih1[n] + bhh1[n];
    }
    sm[OFF_C0 + tid] = 0.f;
    sm[OFF_C1 + tid] = 0.f;
    __syncthreads();

    ull acc[16];

    // ===== encoder layer 0 =====
    for (int t = 0; t < TT; t++) {
#pragma unroll
        for (int i = 0; i < 16; i++) acc[i] = 0ull;
        g64(g_xT + (size_t)t * 4096, sm + OFF_WX, sm, acc, warp, cq, bp8);
        if (t > 0)
            g512(g_hs0 + (size_t)(t - 1) * HH * BB, sm + OFF_WHH0, sm, acc,
                 warp, cq, bp8);
        step_finish(sm, acc, warp, cq, bp8, sm + OFF_B0, sm + OFF_C0, cta,
                    g_hs0 + (size_t)t * HH * BB, nullptr);
    }

    // ===== encoder layer 1 =====
    for (int t = 0; t < TT; t++) {
#pragma unroll
        for (int i = 0; i < 16; i++) acc[i] = 0ull;
        g512(g_hs0 + (size_t)t * HH * BB, sm + OFF_WIH1, sm, acc, warp, cq, bp8);
        if (t > 0)
            g512(g_h1buf + (size_t)((t - 1) & 1) * HH * BB, sm + OFF_WHH1, sm, acc,
                 warp, cq, bp8);
        step_finish(sm, acc, warp, cq, bp8, sm + OFF_B1, sm + OFF_C1, cta,
                    g_h1buf + (size_t)(t & 1) * HH * BB, nullptr);
    }

    // ===== decoder =====
    for (int s = 0; s < TGTN; s++) {
        // phase A : layer-0 cell
#pragma unroll
        for (int i = 0; i < 16; i++) acc[i] = 0ull;
        {
            const float* xin = (s == 0) ? (g_xT + (size_t)(TT - 1) * 4096) : g_y;
            g64(xin, sm + OFF_WX, sm, acc, warp, cq, bp8);
            const float* hp = (s == 0) ? (g_hs0 + (size_t)(TT - 1) * HH * BB)
                                       : (g_h0buf + (size_t)((s - 1) & 1) * HH * BB);
            g512(hp, sm + OFF_WHH0, sm, acc, warp, cq, bp8);
            step_finish(sm, acc, warp, cq, bp8, sm + OFF_B0, sm + OFF_C0, cta,
                        g_h0buf + (size_t)(s & 1) * HH * BB, nullptr);
        }
        // phase B : layer-1 cell (writes k-major + b-major copy for fc)
#pragma unroll
        for (int i = 0; i < 16; i++) acc[i] = 0ull;
        {
            g512(g_h0buf + (size_t)(s & 1) * HH * BB, sm + OFF_WIH1, sm, acc,
                 warp, cq, bp8);
            const float* hp = (s == 0) ? (g_h1buf + (size_t)HH * BB)
                                       : (g_h1buf + (size_t)((s - 1) & 1) * HH * BB);
            g512(hp, sm + OFF_WHH1, sm, acc, warp, cq, bp8);
            step_finish(sm, acc, warp, cq, bp8, sm + OFF_B1, sm + OFF_C1, cta,
                        g_h1buf + (size_t)(s & 1) * HH * BB, g_h1T);
        }
        // phase C : y = h1 @ Wfc^T + bfc
        {
            float* sFc = sm + OFF_FC;
            int p = tid >> 3, q = tid & 7;        // 32 outputs/CTA, 8-way K split
            int flat = cta * 32 + p;
            int bb = flat >> 6, oo = flat & 63;
            const float4* h4 = (const float4*)(g_h1T + (size_t)bb * HH + q * 64);
            const float4* w4 = (const float4*)(Wfc + (size_t)oo * HH + q * 64);
            float sum = 0.f;
#pragma unroll
            for (int k = 0; k < 16; k++) {
                float4 a = h4[k], w = w4[k];
                sum += a.x * w.x + a.y * w.y + a.z * w.z + a.w * w.w;
            }
            sFc[p * 8 + q] = sum;
            __syncthreads();
            if (tid < 32) {
                int fl = cta * 32 + tid;
                int bb2 = fl >> 6, oo2 = fl & 63;
                float tot = bfc[oo2];
#pragma unroll
                for (int j = 0; j < 8; j++) tot += sFc[tid * 8 + j];
                g_y[oo2 * 64 + bb2] = tot;     // k-major feedback
                out[(size_t)bb2 * TGTN * OO + (size_t)s * OO + oo2] = tot;
            }
            grid_barrier();
        }
    }
}

// ---- host launch ----
extern "C" void kernel_launch(void* const* d_in, const int* in_sizes, int n_in,
                              void* d_out, int out_size) {
    (void)in_sizes; (void)n_in; (void)out_size;
    const float* x    = (const float*)d_in[0];
    const float* Wih0 = (const float*)d_in[1];
    const float* Whh0 = (const float*)d_in[2];
    const float* bih0 = (const float*)d_in[3];
    const float* bhh0 = (const float*)d_in[4];
    const float* Wih1 = (const float*)d_in[5];
    const float* Whh1 = (const float*)d_in[6];
    const float* bih1 = (const float*)d_in[7];
    const float* bhh1 = (const float*)d_in[8];
    const float* Wfc  = (const float*)d_in[9];
    const float* bfc  = (const float*)d_in[10];

    prep_w_kernel<<<NCTA, NTHR>>>(Wih0, Whh0, Wih1, Whh1);
    prep_x_kernel<<<TT, NTHR>>>(x);

    cudaFuncSetAttribute(lstm_persistent_kernel,
                         cudaFuncAttributeMaxDynamicSharedMemorySize, SMEM_BYTES);
    lstm_persistent_kernel<<<NCTA, NTHR, SMEM_BYTES>>>(
        bih0, bhh0, bih1, bhh1, Wfc, bfc, (float*)d_out);
}